// round 14
// baseline (speedup 1.0000x reference)
#include <cuda_runtime.h>
#include <cuda_fp16.h>
#include <cstdint>
typedef uint32_t u32;

#define TT 64
#define BB 128
#define HH 256
#define G4H 1024
#define NBLK 64
#define NTHR 256

// fragment-major state arrays: unit (kt,row) = 32B, half order within unit:
// [k(2q),k(2q+1),k(2q+8),k(2q+9)] for q=0..3.
__device__ uint4 g_xF4[TT*16*BB*2];      // x, converted+permuted once
__device__ uint4 g_h0nF4[2][16*BB*2];    // fresh layer0 hidden (layer1 input)
__device__ uint4 g_h0sF4[2][16*BB*2];    // layer0 carried state
__device__ uint4 g_h1sF4[2][16*BB*2];    // layer1 carried state
__device__ unsigned g_flags[NBLK];       // flag idx == bid; 16 per group = 64B line
__device__ unsigned g_ctr0, g_gen0;      // init barrier only (monotonic)

__device__ __forceinline__ float sigf(float v){ return 1.0f/(1.0f+__expf(-v)); }

__device__ __forceinline__ unsigned ldacq(const unsigned* p){
  unsigned v; asm volatile("ld.global.acquire.gpu.u32 %0, [%1];" : "=r"(v) : "l"(p) : "memory");
  return v;
}
__device__ __forceinline__ void strel(unsigned* p, unsigned v){
  asm volatile("st.global.release.gpu.u32 [%0], %1;" :: "l"(p), "r"(v) : "memory");
}

// m16n8k16 fp16 mma, fp32 accum
__device__ __forceinline__ void hmma(float* d, u32 a0, u32 a1, u32 a2, u32 a3, uint2 b){
  asm volatile("mma.sync.aligned.m16n8k16.row.col.f32.f16.f16.f32 "
    "{%0,%1,%2,%3}, {%4,%5,%6,%7}, {%8,%9}, {%0,%1,%2,%3};"
    : "+f"(d[0]),"+f"(d[1]),"+f"(d[2]),"+f"(d[3])
    : "r"(a0),"r"(a1),"r"(a2),"r"(a3), "r"(b.x),"r"(b.y));
}

// init-only central barrier (monotonic gen, replay-safe)
__device__ __forceinline__ void init_arrive_and_wait(unsigned base){
  __syncthreads();
  if (threadIdx.x == 0){
    __threadfence();
    unsigned old = atomicAdd(&g_ctr0, 1u);
    if (old == (unsigned)(NBLK-1)){
      *(volatile unsigned*)&g_ctr0 = 0u;
      __threadfence();
      atomicAdd(&g_gen0, 1u);
    }
    while (*(volatile unsigned*)&g_gen0 - base < 1u){ }
    __threadfence();
  }
  __syncthreads();
}

// PER-WARP wait: all 16 flags of group (base idx gb) >= tgt. One 64B line.
__device__ __forceinline__ void wait_flags_w(int gb, unsigned tgt){
  const unsigned* p = &g_flags[gb + (threadIdx.x & 15)];
  unsigned v = ldacq(p);
  while (!__all_sync(0xffffffffu, v >= tgt)) v = ldacq(p);
}

// one 256-k source (16 k-tiles): per kt per lane 2 coalesced LDG.64 feeding
// 4 n-tiles (one per GATE). Even/odd ktl accumulator chains.
__device__ __forceinline__ void compute_frag(
    const uint2* __restrict__ F, const uint2* __restrict__ wf,
    int kbase, int b1q, int b2q, int lane,
    float accE[4][4], float accO[4][4])
{
  #pragma unroll
  for (int ktl = 0; ktl < 16; ktl++){
    uint2 va = __ldcg(F + ktl*512 + b1q);
    uint2 vb = __ldcg(F + ktl*512 + b2q);
    int kt = kbase + ktl;
    #pragma unroll
    for (int g = 0; g < 4; g++){
      uint2 w = wf[g*1024 + kt*32 + lane];
      hmma((ktl & 1) ? accO[g] : accE[g], va.x, vb.x, va.y, vb.y, w);
    }
  }
}

__global__ void __launch_bounds__(NTHR, 1) stacklstm_h16(
    const float* __restrict__ x,   const int* __restrict__ ops,
    const float* __restrict__ Wih, const float* __restrict__ Whh,
    const float* __restrict__ bih, const float* __restrict__ bhh,
    float* __restrict__ out)
{
  extern __shared__ uint2 wfrag[];   // [wc2][g4][kt32][lane32] = 8192 uint2 = 64KB

  const int tid = threadIdx.x, bid = blockIdx.x;
  const int wid = tid >> 5, lane = tid & 31;
  const int layer = bid >> 5;            // 0 / 1
  const int bh    = (bid >> 4) & 1;      // batch half
  const int cg    = bid & 15;            // 16 j's per block
  const int j0    = cg * 16;
  const int b0    = bh * 64;
  const int wr2   = wid >> 1;            // 4 row groups of 16
  const int wc    = wid & 1;             // 2 col sub-blocks of 8 j's

  const int own_g = bid & ~15;           // own flag-group base (== group*16)
  const int l0_g  = own_g - 32;          // layer1's matching layer0 group
  const int l1_g  = own_g + 32;          // layer0's matching layer1 group

  const float* Wi = Wih + layer*G4H*HH;
  const float* Wh = Whh + layer*G4H*HH;

  // ---- W fragment pack (once): [wc2][g4][kt32][lane32] ----
  for (int idx = tid; idx < 8192; idx += NTHR){
    int ln  = idx & 31;
    int kt  = (idx >> 5) & 31;
    int g   = (idx >> 10) & 3;
    int wc2 = idx >> 12;
    int wrow = g*HH + j0 + wc2*8 + (ln >> 2);
    int k0 = kt*16 + (ln & 3)*2;
    const float* sw = (kt < 16) ? (Wi + wrow*HH + k0) : (Wh + wrow*HH + k0 - HH);
    __half2 p0 = __halves2half2(__float2half_rn(__ldg(sw)),   __float2half_rn(__ldg(sw+1)));
    __half2 p1 = __halves2half2(__float2half_rn(__ldg(sw+8)), __float2half_rn(__ldg(sw+9)));
    wfrag[idx] = make_uint2(*(u32*)&p0, *(u32*)&p1);
  }

  // per-thread EW constants: cells (b1, jl0), (b1, jl1), (b1+8, jl0), (b1+8, jl1)
  const int q   = lane & 3;
  const int jl0 = 2*q;                          // local j within warp's 8
  const int jg0 = j0 + wc*8 + jl0;              // global j (even)
  const int b1  = b0 + wr2*16 + (lane >> 2);
  float biasv[4][2];
  #pragma unroll
  for (int g = 0; g < 4; g++)
    #pragma unroll
    for (int s = 0; s < 2; s++){
      int wrow = g*HH + jg0 + s;
      biasv[g][s] = __ldg(bih + layer*G4H + wrow) + __ldg(bhh + layer*G4H + wrow);
    }

  // ---- x -> fragment-major fp16 (once) ----
  #pragma unroll 1
  for (int u0 = 0; u0 < 8; u0++){
    int u = u0*(NBLK*NTHR) + bid*NTHR + tid;   // 0..131071
    int t   = u >> 11;
    int kt  = (u >> 7) & 15;
    int row = u & 127;
    const float* sp = x + (t*BB + row)*HH + kt*16;
    float4 f0 = __ldg((const float4*)sp);
    float4 f1 = __ldg((const float4*)(sp+4));
    float4 f2 = __ldg((const float4*)(sp+8));
    float4 f3 = __ldg((const float4*)(sp+12));
    __half2 d0 = __halves2half2(__float2half_rn(f0.x), __float2half_rn(f0.y));
    __half2 d1 = __halves2half2(__float2half_rn(f2.x), __float2half_rn(f2.y));
    __half2 d2 = __halves2half2(__float2half_rn(f0.z), __float2half_rn(f0.w));
    __half2 d3 = __halves2half2(__float2half_rn(f2.z), __float2half_rn(f2.w));
    __half2 d4 = __halves2half2(__float2half_rn(f1.x), __float2half_rn(f1.y));
    __half2 d5 = __halves2half2(__float2half_rn(f3.x), __float2half_rn(f3.y));
    __half2 d6 = __halves2half2(__float2half_rn(f1.z), __float2half_rn(f1.w));
    __half2 d7 = __halves2half2(__float2half_rn(f3.z), __float2half_rn(f3.w));
    uint4* dst = g_xF4 + (size_t)((t*16 + kt)*128 + row)*2;
    dst[0] = make_uint4(*(u32*)&d0, *(u32*)&d1, *(u32*)&d2, *(u32*)&d3);
    dst[1] = make_uint4(*(u32*)&d4, *(u32*)&d5, *(u32*)&d6, *(u32*)&d7);
  }
  // zero parity-0 state frags + own flag
  { int idx = bid*NTHR + tid;
    if (idx < 16*BB*2){
      g_h0sF4[0][idx] = make_uint4(0,0,0,0);
      g_h1sF4[0][idx] = make_uint4(0,0,0,0);
    } }
  if (tid == 0) g_flags[bid] = 0u;

  unsigned base0 = 0;
  if (tid == 0) base0 = *(volatile unsigned*)&g_gen0;
  init_arrive_and_wait(base0);   // zeros + x frags + flags visible after

  float c[4]  = {0.f,0.f,0.f,0.f};
  float hk[4] = {0.f,0.f,0.f,0.f};
  const int b1q = b1*4 + q, b2q = (b1+8)*4 + q;
  const int ktv = cg;                              // block covers exactly kt=cg
  const int fo0 = q*4 + wc*2;                      // fragoff(wc*8 + 2q), even
  const uint2* wf = wfrag + wc*4096;

  for (int t = 0; t < TT; t++){
    float accE[4][4] = {}, accO[4][4] = {};

    if (layer == 0){
      // x half: no dependency — compute before any wait
      compute_frag((const uint2*)(g_xF4 + (size_t)t*16*128*2), wf, 0,
                   b1q, b2q, lane, accE, accO);
      if (t >= 1) wait_flags_w(own_g, (unsigned)t);       // own done t-1 (h0s)
      compute_frag((const uint2*)g_h0sF4[t&1], wf, 16,
                   b1q, b2q, lane, accE, accO);
      if (t >= 2) wait_flags_w(l1_g, (unsigned)(t-1));    // L1 done t-2 (h0n free)
    } else {
      if (t >= 1) wait_flags_w(own_g, (unsigned)t);       // own done t-1 (h1s)
      compute_frag((const uint2*)g_h1sF4[t&1], wf, 16,
                   b1q, b2q, lane, accE, accO);
      wait_flags_w(l0_g, (unsigned)(t+1));                // L0 done t (h0n ready)
      compute_frag((const uint2*)g_h0nF4[t&1], wf, 0,
                   b1q, b2q, lane, accE, accO);
    }

    // ---- LSTM elementwise: all 4 gates local to the thread (no shfl) ----
    {
      const int op0 = __ldg(ops + t*BB + b1);
      const int op1 = __ldg(ops + t*BB + b1 + 8);
      __half2 fr[2], kp[2];                       // [row-pair] packed (jl0,jl1)
      float fof[4];                               // fp32 fresh for layer1 out
      #pragma unroll
      for (int i = 0; i < 4; i++){
        int s = i & 1;
        float gi = accE[0][i] + accO[0][i] + biasv[0][s];
        float gf = accE[1][i] + accO[1][i] + biasv[1][s];
        float gg = accE[2][i] + accO[2][i] + biasv[2][s];
        float go = accE[3][i] + accO[3][i] + biasv[3][s];
        float cn = sigf(gf)*c[i] + sigf(gi)*tanhf(gg);
        float hn = sigf(go)*tanhf(cn);
        int op = (i < 2) ? op0 : op1;
        if (op){ c[i] = cn; hk[i] = hn; }
        fof[i] = hn;
        if (s){ fr[i>>1] = __halves2half2(__float2half_rn(fof[i-1]), __float2half_rn(hn));
                kp[i>>1] = __halves2half2(__float2half_rn(hk[i-1]),  __float2half_rn(hk[i])); }
      }
      const int u0 = ((ktv*128 + b1)*16 + fo0) >> 1;        // half2 index, row b1
      const int u1 = ((ktv*128 + b1 + 8)*16 + fo0) >> 1;    // row b1+8
      if (layer == 0){
        __half2* fresh = (__half2*)g_h0nF4[t&1];
        __half2* keep  = (__half2*)g_h0sF4[(t+1)&1];
        fresh[u0] = fr[0]; fresh[u1] = fr[1];
        keep[u0]  = kp[0]; keep[u1]  = kp[1];
      } else {
        float* fresh = out + t*BB*HH;
        __half2* keep = (__half2*)g_h1sF4[(t+1)&1];
        *(float2*)(fresh + b1*HH + jg0)     = make_float2(fof[0], fof[1]);
        *(float2*)(fresh + (b1+8)*HH + jg0) = make_float2(fof[2], fof[3]);
        keep[u0]  = kp[0]; keep[u1]  = kp[1];
      }
    }

    __syncthreads();                               // all warps' EW stores issued
    if (tid == 0) strel(&g_flags[bid], (unsigned)(t+1));
  }
}

extern "C" void kernel_launch(void* const* d_in, const int* in_sizes, int n_in,
                              void* d_out, int out_size)
{
  const float* x   = (const float*)d_in[0];
  const int*   ops = (const int*)  d_in[1];
  const float* Wih = (const float*)d_in[2];
  const float* Whh = (const float*)d_in[3];
  const float* bih = (const float*)d_in[4];
  const float* bhh = (const float*)d_in[5];
  float* out = (float*)d_out;
  cudaFuncSetAttribute(stacklstm_h16, cudaFuncAttributeMaxDynamicSharedMemorySize, 65536);
  stacklstm_h16<<<NBLK, NTHR, 65536>>>(x, ops, Wih, Whh, bih, bhh, out);
}